// round 13
// baseline (speedup 1.0000x reference)
#include <cuda_runtime.h>
#include <math.h>

#define D 64
#define KD 32
#define MAXU 50000
#define MAXI 30000
#define MAXENT 100000
#define MAXE 500000
#define MAXEI 1000000
#define MAXREL 10
#define GAMMA 0.2f
#define SCHUNK 1024
#define NBKT 64

typedef unsigned long long u64;

// ---------------- scratch (device globals; no allocation) ----------------
__device__ float g_userWq[MAXU * D];
__device__ float g_itemWk[MAXI * D];
__device__ float g_itemWv[MAXI * D];
__device__ float g_scoresG[MAXEI];
__device__ float g_itemCoeff[MAXI];
__device__ float g_pref[D];
__device__ float g_qc[D + 1];
__device__ float g_omegaG[MAXE];
__device__ int2 g_epackA[MAXE];      // {tpack, alpha bits} per CSR-E slot
__device__ int2 g_epackB[MAXE];      // {tpack, eta bits}
__device__ float g_embA[MAXENT * D];
__device__ float g_embB[MAXENT * D];
__device__ int g_degE[MAXENT];
__device__ int g_rowE[MAXENT + 1];
__device__ int g_curE[MAXENT];
__device__ int g_posE[MAXE];
__device__ int g_tpackE[MAXE];
__device__ int g_degU[MAXU];
__device__ int g_rowU[MAXU + 1];
__device__ int g_curU[MAXU];
__device__ int g_itemG[MAXEI];
__device__ float g_wG[MAXEI];
__device__ int g_bsum[1024];
__device__ int g_boff[1024];
__device__ int g_bkt[2 * NBKT];
__device__ int g_bktcur[2 * NBKT];
__device__ int g_permE[MAXENT];
__device__ int g_permU[MAXU];
// precomputed per-entity tables
__device__ float g_Ah[MAXENT * D];
__device__ float g_At[MAXENT * D];
__device__ float g_P[MAXENT * D];
__device__ float g_Arel[MAXREL * D];
__device__ float g_Prel[MAXREL * D];

// ---------------- helpers ----------------
__device__ __forceinline__ float n2n(float x) {
    if (x != x) return 0.f;
    if (x == INFINITY) return 1e4f;
    if (x == -INFINITY) return 1e-4f;
    return x;
}
__device__ __forceinline__ float sigm(float x) {
    return __fdividef(1.f, 1.f + __expf(-x));
}
__device__ __forceinline__ u64 pack2(float x, float y) {
    u64 r;
    asm("mov.b64 %0, {%1, %2};" : "=l"(r) : "f"(x), "f"(y));
    return r;
}
__device__ __forceinline__ u64 ffma2(u64 a, u64 b, u64 c) {
    u64 d;
    asm("fma.rn.f32x2 %0, %1, %2, %3;" : "=l"(d) : "l"(a), "l"(b), "l"(c));
    return d;
}
__device__ __forceinline__ float red16(float v) {
#pragma unroll
    for (int o = 8; o; o >>= 1) v += __shfl_xor_sync(0xffffffffu, v, o);
    return v;
}
__device__ __forceinline__ float red32(float v) {
#pragma unroll
    for (int o = 16; o; o >>= 1) v += __shfl_xor_sync(0xffffffffu, v, o);
    return v;
}

// ---------------- init ----------------
__global__ void zero_kernel(int* degE, int* degU, float* ic, float* pref,
                            int* bkt, int NE, int NU, int NI) {
    int i = blockIdx.x * blockDim.x + threadIdx.x;
    if (i < NE) degE[i] = 0;
    if (i < NU) degU[i] = 0;
    if (i < NI) ic[i] = 0.f;
    if (i < 64) pref[i] = 0.f;
    if (i < 2 * NBKT) bkt[i] = 0;
}

__global__ void hist2_kernel(const int* __restrict__ eh, const int* __restrict__ users,
                             int* degE, int* degU, int E, int EI) {
    int i = blockIdx.x * blockDim.x + threadIdx.x;
    if (i < E) atomicAdd(&degE[eh[i]], 1);
    else if (i < E + EI) atomicAdd(&degU[users[i - E]], 1);
}

// ---------------- 3-phase parallel exclusive scan (E and U fused) ----------
__global__ void bsum_kernel(const int* __restrict__ degE, int NE,
                            const int* __restrict__ degU, int NU,
                            int* bsum, int nBE) {
    __shared__ int wsum[32];
    int b = blockIdx.x;
    bool isE = b < nBE;
    const int* deg = isE ? degE : degU;
    int n = isE ? NE : NU;
    int base = (isE ? b : (b - nBE)) * SCHUNK;
    int i = base + threadIdx.x;
    int v = (i < n) ? deg[i] : 0;
    int lane = threadIdx.x & 31, wid = threadIdx.x >> 5;
#pragma unroll
    for (int o = 16; o; o >>= 1) v += __shfl_xor_sync(0xffffffffu, v, o);
    if (lane == 0) wsum[wid] = v;
    __syncthreads();
    if (wid == 0) {
        int s = wsum[lane];
#pragma unroll
        for (int o = 16; o; o >>= 1) s += __shfl_xor_sync(0xffffffffu, s, o);
        if (lane == 0) bsum[b] = s;
    }
}

__global__ void bscan_kernel(const int* __restrict__ bsum, int* boff, int nBE, int nB,
                             int* rowE, int NE, int* rowU, int NU) {
    __shared__ int sh[1024];
    int tid = threadIdx.x;
    for (int i = tid; i < nB; i += blockDim.x) sh[i] = bsum[i];
    __syncthreads();
    if (tid == 0) {
        int acc = 0;
        for (int i = 0; i < nBE; i++) { int v = sh[i]; sh[i] = acc; acc += v; }
        rowE[NE] = acc;
    }
    if (tid == 1) {
        int acc = 0;
        for (int i = nBE; i < nB; i++) { int v = sh[i]; sh[i] = acc; acc += v; }
        rowU[NU] = acc;
    }
    __syncthreads();
    for (int i = tid; i < nB; i += blockDim.x) boff[i] = sh[i];
}

__global__ void bexpand_kernel(const int* __restrict__ degE, int NE,
                               const int* __restrict__ degU, int NU,
                               const int* __restrict__ boff, int nBE,
                               int* rowE, int* rowU, int* curE, int* curU,
                               int* bkt) {
    __shared__ int wsum[32];
    int b = blockIdx.x;
    bool isE = b < nBE;
    const int* deg = isE ? degE : degU;
    int n = isE ? NE : NU;
    int* row = isE ? rowE : rowU;
    int* cur = isE ? curE : curU;
    int base = (isE ? b : (b - nBE)) * SCHUNK;
    int i = base + threadIdx.x;
    int v = (i < n) ? deg[i] : 0;
    int lane = threadIdx.x & 31, wid = threadIdx.x >> 5;
    int s = v;
#pragma unroll
    for (int o = 1; o < 32; o <<= 1) {
        int t = __shfl_up_sync(0xffffffffu, s, o);
        if (lane >= o) s += t;
    }
    if (lane == 31) wsum[wid] = s;
    __syncthreads();
    if (wid == 0) {
        int ws = wsum[lane];
#pragma unroll
        for (int o = 1; o < 32; o <<= 1) {
            int t = __shfl_up_sync(0xffffffffu, ws, o);
            if (lane >= o) ws += t;
        }
        wsum[lane] = ws;
    }
    __syncthreads();
    int excl = ((wid == 0) ? 0 : wsum[wid - 1]) + s - v + boff[b];
    if (i < n) {
        row[i] = excl;
        cur[i] = excl;
        // degree-bucket histogram for row scheduling
        int bk = (v < NBKT) ? v : (NBKT - 1);
        atomicAdd(&bkt[(isE ? 0 : NBKT) + bk], 1);
    }
}

// scan the 2*NBKT degree buckets into cursors (tiny)
__global__ void bktscan_kernel(const int* __restrict__ bkt, int* bktcur) {
    int tid = threadIdx.x;
    if (tid == 0) {
        int acc = 0;
        for (int i = 0; i < NBKT; i++) { int v = bkt[i]; bktcur[i] = acc; acc += v; }
    }
    if (tid == 1) {
        int acc = 0;
        for (int i = NBKT; i < 2 * NBKT; i++) { int v = bkt[i]; bktcur[i] = acc; acc += v; }
    }
}

// place rows into degree-sorted permutation
__global__ void bktfill_kernel(const int* __restrict__ degE, int NE,
                               const int* __restrict__ degU, int NU,
                               int* bktcur, int* permE, int* permU) {
    int i = blockIdx.x * blockDim.x + threadIdx.x;
    if (i < NE) {
        int v = degE[i];
        int bk = (v < NBKT) ? v : (NBKT - 1);
        int p = atomicAdd(&bktcur[bk], 1);
        permE[p] = i;
    }
    if (i < NU) {
        int v = degU[i];
        int bk = (v < NBKT) ? v : (NBKT - 1);
        int p = atomicAdd(&bktcur[NBKT + bk], 1);
        permU[p] = i;
    }
}

__global__ void fill2_kernel(const int* __restrict__ eh, const int* __restrict__ et,
                             const int* __restrict__ etype, int* curE, int* posE, int* tpackE,
                             int E,
                             const int* __restrict__ users, const int* __restrict__ items,
                             const float* __restrict__ w, int* curU,
                             int* itemG, float* wG, int EI) {
    int i = blockIdx.x * blockDim.x + threadIdx.x;
    if (i < E) {
        int p = atomicAdd(&curE[eh[i]], 1);
        posE[i] = p;
        tpackE[p] = et[i] | ((etype[i] - 1) << 20);
    } else if (i < E + EI) {
        int e = i - E;
        int p = atomicAdd(&curU[users[e]], 1);
        itemG[p] = items[e];
        wG[p] = w[e];
    }
}

// ---------------- entity precompute: Ah, At, P ----------------
__global__ void entpre_kernel(const float* __restrict__ ent_real,
                              const float* __restrict__ ent_imag,
                              const float* __restrict__ fpW1,
                              const float* __restrict__ rtW1,
                              float* __restrict__ Ah, float* __restrict__ At,
                              float* __restrict__ P, int NE) {
    __shared__ float sWa[64 * 64];
    __shared__ float sWb[64 * 64];
    __shared__ float sWp[64 * 64];
    __shared__ float sX[32 * 64];
    int tid = threadIdx.x;  // 1024
    for (int i = tid; i < 4096; i += 1024) {
        sWa[i] = fpW1[i];
        sWb[i] = fpW1[128 * 64 + i];
        sWp[i] = rtW1[i];
    }
    int rowBase = blockIdx.x * 32;
    for (int i = tid; i < 32 * 64; i += 1024) {
        int rl = i >> 6, k = i & 63;
        int n = rowBase + rl;
        float v = 0.f;
        if (n < NE) v = (k < 32) ? ent_real[n * KD + k] : ent_imag[n * KD + (k - 32)];
        sX[i] = v;
    }
    __syncthreads();
    int rl = tid >> 5, jp = tid & 31;
    int n = rowBase + rl;
    if (n >= NE) return;
    u64 a0 = 0, a1 = 0, a2 = 0;
    const u64* wa = (const u64*)sWa;
    const u64* wb = (const u64*)sWb;
    const u64* wp = (const u64*)sWp;
#pragma unroll 8
    for (int k = 0; k < 64; k++) {
        float xv = sX[rl * 64 + k];
        u64 xx = pack2(xv, xv);
        a0 = ffma2(xx, wa[k * 32 + jp], a0);
        a1 = ffma2(xx, wb[k * 32 + jp], a1);
        a2 = ffma2(xx, wp[k * 32 + jp], a2);
    }
    ((u64*)Ah)[n * 32 + jp] = a0;
    ((u64*)At)[n * 32 + jp] = a1;
    ((u64*)P)[n * 32 + jp] = a2;
}

// ---------------- relation precompute ----------------
__global__ void relpre_kernel(const float* __restrict__ rel_real,
                              const float* __restrict__ rel_imag,
                              const float* __restrict__ fpW1,
                              const float* __restrict__ rtW1,
                              float* __restrict__ Arel, float* __restrict__ Prel, int NR) {
    int tid = threadIdx.x;
    int r = tid >> 6, j = tid & 63;
    if (r >= NR) return;
    float a = 0.f, p = 0.f;
    for (int k = 0; k < 64; k++) {
        float xv = (k < 32) ? rel_real[r * KD + k] : rel_imag[r * KD + (k - 32)];
        a += xv * fpW1[(64 + k) * 64 + j];
        p += xv * rtW1[k * 64 + j];
    }
    Arel[r * 64 + j] = a;
    Prel[r * 64 + j] = p;
}

// ---------------- merged projections: blocks [0,gU) do Q, [gU,gU+gI) do K+V
__global__ void gemmQKV_kernel(const float* __restrict__ Xu, const float* __restrict__ Wq,
                               const float* __restrict__ Xi, const float* __restrict__ Wk,
                               const float* __restrict__ Wv,
                               float* __restrict__ Yq, float* __restrict__ Yk,
                               float* __restrict__ Yv, int NU, int NI, int gU) {
    __shared__ float sW0[64 * 64];
    __shared__ float sW1[64 * 64];
    __shared__ float sX[16 * 64];
    int tid = threadIdx.x;
    int b = blockIdx.x;
    int r = tid >> 6, j = tid & 63;
    if (b < gU) {
        for (int i = tid; i < 4096; i += 1024) sW0[i] = Wq[i];
        int row = b * 16 + r;
        if (row < NU) sX[r * 64 + j] = Xu[row * 64 + j];
        __syncthreads();
        if (row < NU) {
            float acc = 0.f;
#pragma unroll
            for (int k = 0; k < 64; k++) acc += sX[r * 64 + k] * sW0[k * 64 + j];
            Yq[row * 64 + j] = acc;
        }
    } else {
        for (int i = tid; i < 4096; i += 1024) {
            sW0[i] = Wk[i];
            sW1[i] = Wv[i];
        }
        int row = (b - gU) * 16 + r;
        if (row < NI) sX[r * 64 + j] = Xi[row * 64 + j];
        __syncthreads();
        if (row < NI) {
            float ak = 0.f, av = 0.f;
#pragma unroll
            for (int k = 0; k < 64; k++) {
                float xv = sX[r * 64 + k];
                ak += xv * sW0[k * 64 + j];
                av += xv * sW1[k * 64 + j];
            }
            Yk[row * 64 + j] = ak;
            Yv[row * 64 + j] = av;
        }
    }
}

// ---------------- fused miner v2: warp per user, q register-resident ------
__global__ void miner2_kernel(const float* __restrict__ uq, const float* __restrict__ ik,
                              const int* __restrict__ rowU, const int* __restrict__ itemG,
                              const float* __restrict__ wG,
                              float* __restrict__ scoresG, float* itemCoeff, int NU) {
    int gw = (blockIdx.x * blockDim.x + threadIdx.x) >> 5;
    int lane = threadIdx.x & 31;
    if (gw >= NU) return;
    int u = gw;
    int s = rowU[u], e = rowU[u + 1];
    int deg = e - s;
    if (deg == 0) return;
    float2 q = ((const float2*)uq)[(size_t)u * 32 + lane];
    const float2* ik2 = (const float2*)ik;

    int i = s;
    for (; i + 4 <= e; i += 4) {
        int it0 = itemG[i], it1 = itemG[i + 1], it2 = itemG[i + 2], it3 = itemG[i + 3];
        float2 k0 = ik2[(size_t)it0 * 32 + lane];
        float2 k1 = ik2[(size_t)it1 * 32 + lane];
        float2 k2 = ik2[(size_t)it2 * 32 + lane];
        float2 k3 = ik2[(size_t)it3 * 32 + lane];
        float d0 = q.x * k0.x + q.y * k0.y;
        float d1 = q.x * k1.x + q.y * k1.y;
        float d2 = q.x * k2.x + q.y * k2.y;
        float d3 = q.x * k3.x + q.y * k3.y;
        d0 = red32(d0);
        d1 = red32(d1);
        d2 = red32(d2);
        d3 = red32(d3);
        if (lane < 4) {
            float dj = (lane == 0) ? d0 : (lane == 1) ? d1 : (lane == 2) ? d2 : d3;
            scoresG[i + lane] = dj * 0.125f * wG[i + lane];
        }
    }
    for (; i < e; i++) {
        float2 k0 = ik2[(size_t)itemG[i] * 32 + lane];
        float d0 = red32(q.x * k0.x + q.y * k0.y);
        if (lane == 0) scoresG[i] = d0 * 0.125f * wG[i];
    }
    __threadfence_block();
    __syncwarp();

    float m = -INFINITY;
    for (int j = s + lane; j < e; j += 32) m = fmaxf(m, scoresG[j]);
#pragma unroll
    for (int o = 16; o; o >>= 1) m = fmaxf(m, __shfl_xor_sync(0xffffffffu, m, o));
    float den = 0.f;
    for (int j = s + lane; j < e; j += 32) den += __expf(scoresG[j] - m);
    den = red32(den);
    float invc = __fdividef(1.f, den * fmaxf((float)deg, 1.f));
    for (int j = s + lane; j < e; j += 32)
        atomicAdd(&itemCoeff[itemG[j]], __expf(scoresG[j] - m) * invc);
}

__global__ void pref_kernel(const float* __restrict__ itemCoeff,
                            const float* __restrict__ itemWv, float* pref, int NI) {
    int j = threadIdx.x;  // 64
    float acc = 0.f;
    for (int i = blockIdx.x; i < NI; i += gridDim.x)
        acc += itemCoeff[i] * itemWv[i * 64 + j];
    atomicAdd(&pref[j], acc);
}

__global__ void qc_kernel(const float* __restrict__ rtW2, const float* __restrict__ rtb2,
                          const float* __restrict__ pref, float* qc) {
    __shared__ float sp[64];
    __shared__ float red[64];
    int j = threadIdx.x;
    sp[j] = pref[j];
    __syncthreads();
    float q = 0.f;
#pragma unroll
    for (int k = 0; k < 64; k++) q += rtW2[j * 64 + k] * sp[k];
    qc[j] = q * 0.125f;
    red[j] = rtb2[j] * sp[j];
    __syncthreads();
    if (j == 0) {
        float c = 0.f;
        for (int k = 0; k < 64; k++) c += red[k];
        qc[64] = c * 0.125f;
    }
}

// ---------------- omega: 16-lane subwarp per edge ----------------
__global__ void omega_kernel(const float* __restrict__ Ah, const float* __restrict__ At,
                             const float* __restrict__ P,
                             const float* __restrict__ Arel, const float* __restrict__ Prel,
                             const int* __restrict__ eh, const int* __restrict__ et,
                             const int* __restrict__ etype,
                             const float* __restrict__ fpb1, const float* __restrict__ fpW2,
                             const float* __restrict__ fpb2, const float* __restrict__ rtb1,
                             const float* __restrict__ qc, const int* __restrict__ posE,
                             float* __restrict__ omegaG, int NR, int E) {
    __shared__ float sAr[MAXREL * 64];
    __shared__ float sPr[MAXREL * 64];
    __shared__ float sb1[64], srb1[64], sq[64];
    __shared__ float sW2c0[64], sW2c1[64], sW2c2[64];
    __shared__ float sb2[3];
    __shared__ float sc0;
    int tid = threadIdx.x;
    for (int i = tid; i < NR * 64; i += blockDim.x) {
        sAr[i] = Arel[i];
        sPr[i] = Prel[i];
    }
    for (int i = tid; i < 64; i += blockDim.x) {
        sb1[i] = fpb1[i];
        srb1[i] = rtb1[i];
        sq[i] = qc[i];
        sW2c0[i] = fpW2[i * 3 + 0];
        sW2c1[i] = fpW2[i * 3 + 1];
        sW2c2[i] = fpW2[i * 3 + 2];
    }
    if (tid < 3) sb2[tid] = fpb2[tid];
    if (tid == 0) sc0 = qc[64];
    __syncthreads();

    int g = blockIdx.x * blockDim.x + tid;
    int e = g >> 4, lane = g & 15;
    if (e >= E) return;
    int h = eh[e], t = et[e], r = etype[e] - 1;

    float4 a = ((const float4*)(Ah + (size_t)h * 64))[lane];
    float4 c = ((const float4*)(At + (size_t)t * 64))[lane];
    float4 ph = ((const float4*)(P + (size_t)h * 64))[lane];
    float4 pt = ((const float4*)(P + (size_t)t * 64))[lane];
    float4 b = ((const float4*)(sAr + r * 64))[lane];
    float4 bb = ((const float4*)sb1)[lane];
    float s0 = sigm(a.x + b.x + c.x + bb.x);
    float s1 = sigm(a.y + b.y + c.y + bb.y);
    float s2 = sigm(a.z + b.z + c.z + bb.z);
    float s3 = sigm(a.w + b.w + c.w + bb.w);

    float4 w20 = ((const float4*)sW2c0)[lane];
    float4 w21 = ((const float4*)sW2c1)[lane];
    float4 w22 = ((const float4*)sW2c2)[lane];
    float z0 = s0 * w20.x + s1 * w20.y + s2 * w20.z + s3 * w20.w;
    float z1 = s0 * w21.x + s1 * w21.y + s2 * w21.z + s3 * w21.w;
    float z2 = s0 * w22.x + s1 * w22.y + s2 * w22.z + s3 * w22.w;
    z0 = red16(z0);
    z1 = red16(z1);
    z2 = red16(z2);
    z0 += sb2[0];
    z1 += sb2[1];
    z2 += sb2[2];
    float mx = fmaxf(z0, fmaxf(z1, z2));
    float e0 = __expf(z0 - mx), e1 = __expf(z1 - mx), e2 = __expf(z2 - mx);
    float inv = __fdividef(1.f, e0 + e1 + e2);
    float w0 = e0 * inv, w1 = e1 * inv, w2 = e2 * inv;

    float4 pr = ((const float4*)(sPr + r * 64))[lane];
    float4 rb = ((const float4*)srb1)[lane];
    float4 qv = ((const float4*)sq)[lane];
    float om = qv.x * sigm(w0 * ph.x + w1 * pr.x + w2 * pt.x + rb.x)
             + qv.y * sigm(w0 * ph.y + w1 * pr.y + w2 * pt.y + rb.y)
             + qv.z * sigm(w0 * ph.z + w1 * pr.z + w2 * pt.z + rb.z)
             + qv.w * sigm(w0 * ph.w + w1 * pr.w + w2 * pt.w + rb.w);
    om = red16(om);
    if (lane == 0) omegaG[posE[e]] = om + sc0;
}

// ---------------- alpha / eta packed with tpack ----------------
__global__ void alphaeta_kernel(const float* __restrict__ omegaG, const int* __restrict__ rowE,
                                const int* __restrict__ tpackE,
                                int2* __restrict__ epackA, int2* __restrict__ epackB, int NE) {
    int h = blockIdx.x * blockDim.x + threadIdx.x;
    if (h >= NE) return;
    int s = rowE[h], e = rowE[h + 1];
    if (s == e) return;
    float so = 0.f;
    for (int i = s; i < e; i++) so += omegaG[i];
    float d1 = so + 1e-8f;
    float se = 0.f;
    for (int i = s; i < e; i++) {
        float a = omegaG[i] / d1;
        se += (a > GAMMA) ? a : 0.f;
    }
    float d2 = se + 1e-8f;
    for (int i = s; i < e; i++) {
        float a = omegaG[i] / d1;
        int tp = tpackE[i];
        epackA[i] = make_int2(tp, __float_as_int(a));
        float e0 = (a > GAMMA) ? a / d2 : 0.f;
        epackB[i] = make_int2(tp, __float_as_int(e0));
    }
}

// ---------------- merged hop kernel, degree-sorted row order -------------
__global__ void hop_kernel(const float* __restrict__ src, const float* __restrict__ relemb,
                           const int2* __restrict__ epack,
                           const int* __restrict__ rowE,
                           const int* __restrict__ itemG, const float* __restrict__ wG,
                           const int* __restrict__ rowU,
                           const int* __restrict__ permE, const int* __restrict__ permU,
                           float* __restrict__ dst, float* __restrict__ outE,
                           float* __restrict__ outU,
                           const float* __restrict__ baseE, const float* __restrict__ baseU,
                           int hop0, int writeDst, int NE, int NU, int NR) {
    __shared__ float sRel[MAXREL * 64];
    int tid = threadIdx.x;
    for (int i = tid; i < NR * 64; i += blockDim.x) sRel[i] = relemb[i];
    __syncthreads();

    int g = blockIdx.x * blockDim.x + tid;
    int row = g >> 4, lane = g & 15;
    if (row >= NE + NU) return;
    const float4* src4 = (const float4*)src;

    if (row < NE) {
        int h = permE[row];
        int s = rowE[h], e1 = rowE[h + 1];
        float4 acc = make_float4(0.f, 0.f, 0.f, 0.f);
        int i = s;
        for (; i + 2 <= e1; i += 2) {
            int2 p0 = epack[i], p1 = epack[i + 1];
            float r0 = __int_as_float(p0.y), r1 = __int_as_float(p1.y);
            float4 x0 = src4[(size_t)(p0.x & 0xFFFFF) * 16 + lane];
            float4 x1 = src4[(size_t)(p1.x & 0xFFFFF) * 16 + lane];
            const float4* sRel4 = (const float4*)sRel;
            float4 w0 = sRel4[(p0.x >> 20) * 16 + lane];
            float4 w1 = sRel4[(p1.x >> 20) * 16 + lane];
            acc.x += r0 * x0.x * w0.x + r1 * x1.x * w1.x;
            acc.y += r0 * x0.y * w0.y + r1 * x1.y * w1.y;
            acc.z += r0 * x0.z * w0.z + r1 * x1.z * w1.z;
            acc.w += r0 * x0.w * w0.w + r1 * x1.w * w1.w;
        }
        if (i < e1) {
            int2 p = epack[i];
            float rv = __int_as_float(p.y);
            float4 x = src4[(size_t)(p.x & 0xFFFFF) * 16 + lane];
            const float4* sRel4 = (const float4*)sRel;
            float4 w = sRel4[(p.x >> 20) * 16 + lane];
            acc.x += rv * x.x * w.x;
            acc.y += rv * x.y * w.y;
            acc.z += rv * x.z * w.z;
            acc.w += rv * x.w * w.w;
        }
        float c = fmaxf((float)(e1 - s), 1.f);
        float invc = __fdividef(1.f, c);
        acc.x *= invc; acc.y *= invc; acc.z *= invc; acc.w *= invc;
        float ss = acc.x * acc.x + acc.y * acc.y + acc.z * acc.z + acc.w * acc.w;
        ss = red16(ss);
        float inv = 1.f / fmaxf(sqrtf(ss), 1e-8f);
        float4 o;
        o.x = n2n(acc.x * inv); o.y = n2n(acc.y * inv);
        o.z = n2n(acc.z * inv); o.w = n2n(acc.w * inv);
        if (writeDst) ((float4*)dst)[(size_t)h * 16 + lane] = o;
        float4 o2 = hop0 ? ((const float4*)baseE)[(size_t)h * 16 + lane]
                         : ((float4*)outE)[(size_t)h * 16 + lane];
        o2.x += o.x; o2.y += o.y; o2.z += o.z; o2.w += o.w;
        ((float4*)outE)[(size_t)h * 16 + lane] = o2;
    } else {
        int u = permU[row - NE];
        int s = rowU[u], e1 = rowU[u + 1];
        float4 acc = make_float4(0.f, 0.f, 0.f, 0.f);
        int i = s;
        for (; i + 4 <= e1; i += 4) {
            int it0 = itemG[i], it1 = itemG[i + 1], it2 = itemG[i + 2], it3 = itemG[i + 3];
            float w0 = wG[i], w1 = wG[i + 1], w2 = wG[i + 2], w3 = wG[i + 3];
            float4 x0 = src4[(size_t)it0 * 16 + lane];
            float4 x1 = src4[(size_t)it1 * 16 + lane];
            float4 x2 = src4[(size_t)it2 * 16 + lane];
            float4 x3 = src4[(size_t)it3 * 16 + lane];
            acc.x += w0 * x0.x + w1 * x1.x + w2 * x2.x + w3 * x3.x;
            acc.y += w0 * x0.y + w1 * x1.y + w2 * x2.y + w3 * x3.y;
            acc.z += w0 * x0.z + w1 * x1.z + w2 * x2.z + w3 * x3.z;
            acc.w += w0 * x0.w + w1 * x1.w + w2 * x2.w + w3 * x3.w;
        }
        for (; i < e1; i++) {
            int it = itemG[i];
            float wv = wG[i];
            float4 x = src4[(size_t)it * 16 + lane];
            acc.x += wv * x.x;
            acc.y += wv * x.y;
            acc.z += wv * x.z;
            acc.w += wv * x.w;
        }
        float ss = acc.x * acc.x + acc.y * acc.y + acc.z * acc.z + acc.w * acc.w;
        ss = red16(ss);
        float inv = 1.f / fmaxf(sqrtf(ss), 1e-8f);
        float4 o;
        o.x = n2n(acc.x * inv); o.y = n2n(acc.y * inv);
        o.z = n2n(acc.z * inv); o.w = n2n(acc.w * inv);
        float4 o2 = hop0 ? ((const float4*)baseU)[(size_t)u * 16 + lane]
                         : ((float4*)outU)[(size_t)u * 16 + lane];
        o2.x += o.x; o2.y += o.y; o2.z += o.z; o2.w += o.w;
        ((float4*)outU)[(size_t)u * 16 + lane] = o2;
    }
}

// ---------------- launch ----------------
extern "C" void kernel_launch(void* const* d_in, const int* in_sizes, int n_in,
                              void* d_out, int out_size) {
    const float* user_embed = (const float*)d_in[0];
    const float* item_embed = (const float*)d_in[1];
    const float* Wq = (const float*)d_in[2];
    const float* Wk = (const float*)d_in[3];
    const float* Wv = (const float*)d_in[4];
    const float* ent_real = (const float*)d_in[5];
    const float* ent_imag = (const float*)d_in[6];
    const float* rel_real = (const float*)d_in[7];
    const float* rel_imag = (const float*)d_in[8];
    const float* fp_W1 = (const float*)d_in[9];
    const float* fp_b1 = (const float*)d_in[10];
    const float* fp_W2 = (const float*)d_in[11];
    const float* fp_b2 = (const float*)d_in[12];
    const float* rt_W1 = (const float*)d_in[13];
    const float* rt_b1 = (const float*)d_in[14];
    const float* rt_W2 = (const float*)d_in[15];
    const float* rt_b2 = (const float*)d_in[16];
    const float* relation_emb = (const float*)d_in[17];
    const float* user_emb = (const float*)d_in[18];
    const float* entity_emb = (const float*)d_in[19];
    const float* inter_edge_w = (const float*)d_in[20];
    const int* edge_index = (const int*)d_in[21];
    const int* edge_type = (const int*)d_in[22];
    const int* inter_edge = (const int*)d_in[23];
    float* out = (float*)d_out;

    int NU = in_sizes[0] / D;
    int NI = in_sizes[1] / D;
    int NE = in_sizes[5] / KD;
    int NR = in_sizes[7] / KD;
    int E = in_sizes[22];
    int EI = in_sizes[20];
    const int* eh = edge_index;
    const int* et = edge_index + E;
    const int* users = inter_edge;
    const int* items = inter_edge + EI;

    float *userWq, *itemWk, *itemWv, *scoresG, *itemCoeff, *pref, *qc;
    float *omegaG, *embA, *embB, *wG;
    int2 *epackA, *epackB;
    float *Ah, *At, *P, *Arel, *Prel;
    int *degE, *rowE, *curE, *posE, *tpackE, *degU, *rowU, *curU, *itemG;
    int *bsum, *boff, *bkt, *bktcur, *permE, *permU;
    cudaGetSymbolAddress((void**)&userWq, g_userWq);
    cudaGetSymbolAddress((void**)&itemWk, g_itemWk);
    cudaGetSymbolAddress((void**)&itemWv, g_itemWv);
    cudaGetSymbolAddress((void**)&scoresG, g_scoresG);
    cudaGetSymbolAddress((void**)&itemCoeff, g_itemCoeff);
    cudaGetSymbolAddress((void**)&pref, g_pref);
    cudaGetSymbolAddress((void**)&qc, g_qc);
    cudaGetSymbolAddress((void**)&omegaG, g_omegaG);
    cudaGetSymbolAddress((void**)&epackA, g_epackA);
    cudaGetSymbolAddress((void**)&epackB, g_epackB);
    cudaGetSymbolAddress((void**)&embA, g_embA);
    cudaGetSymbolAddress((void**)&embB, g_embB);
    cudaGetSymbolAddress((void**)&degE, g_degE);
    cudaGetSymbolAddress((void**)&rowE, g_rowE);
    cudaGetSymbolAddress((void**)&curE, g_curE);
    cudaGetSymbolAddress((void**)&posE, g_posE);
    cudaGetSymbolAddress((void**)&tpackE, g_tpackE);
    cudaGetSymbolAddress((void**)&degU, g_degU);
    cudaGetSymbolAddress((void**)&rowU, g_rowU);
    cudaGetSymbolAddress((void**)&curU, g_curU);
    cudaGetSymbolAddress((void**)&itemG, g_itemG);
    cudaGetSymbolAddress((void**)&wG, g_wG);
    cudaGetSymbolAddress((void**)&bsum, g_bsum);
    cudaGetSymbolAddress((void**)&boff, g_boff);
    cudaGetSymbolAddress((void**)&bkt, g_bkt);
    cudaGetSymbolAddress((void**)&bktcur, g_bktcur);
    cudaGetSymbolAddress((void**)&permE, g_permE);
    cudaGetSymbolAddress((void**)&permU, g_permU);
    cudaGetSymbolAddress((void**)&Ah, g_Ah);
    cudaGetSymbolAddress((void**)&At, g_At);
    cudaGetSymbolAddress((void**)&P, g_P);
    cudaGetSymbolAddress((void**)&Arel, g_Arel);
    cudaGetSymbolAddress((void**)&Prel, g_Prel);

    int nBE = (NE + SCHUNK - 1) / SCHUNK;
    int nBU = (NU + SCHUNK - 1) / SCHUNK;
    int nB = nBE + nBU;

    zero_kernel<<<(NE + 255) / 256, 256>>>(degE, degU, itemCoeff, pref, bkt, NE, NU, NI);
    hist2_kernel<<<(E + EI + 255) / 256, 256>>>(eh, users, degE, degU, E, EI);
    bsum_kernel<<<nB, SCHUNK>>>(degE, NE, degU, NU, bsum, nBE);
    bscan_kernel<<<1, 256>>>(bsum, boff, nBE, nB, rowE, NE, rowU, NU);
    bexpand_kernel<<<nB, SCHUNK>>>(degE, NE, degU, NU, boff, nBE, rowE, rowU, curE, curU, bkt);
    bktscan_kernel<<<1, 32>>>(bkt, bktcur);
    bktfill_kernel<<<(NE + 255) / 256, 256>>>(degE, NE, degU, NU, bktcur, permE, permU);
    entpre_kernel<<<(NE + 31) / 32, 1024>>>(ent_real, ent_imag, fp_W1, rt_W1, Ah, At, P, NE);
    fill2_kernel<<<(E + EI + 255) / 256, 256>>>(eh, et, edge_type, curE, posE, tpackE, E,
                                                users, items, inter_edge_w, curU,
                                                itemG, wG, EI);
    relpre_kernel<<<1, NR * 64>>>(rel_real, rel_imag, fp_W1, rt_W1, Arel, Prel, NR);
    {
        int gU = (NU + 15) / 16, gI = (NI + 15) / 16;
        gemmQKV_kernel<<<gU + gI, 1024>>>(user_embed, Wq, item_embed, Wk, Wv,
                                          userWq, itemWk, itemWv, NU, NI, gU);
    }
    {
        long long th = (long long)NU * 32;
        miner2_kernel<<<(int)((th + 255) / 256), 256>>>(userWq, itemWk, rowU, itemG, wG,
                                                        scoresG, itemCoeff, NU);
    }
    pref_kernel<<<256, 64>>>(itemCoeff, itemWv, pref, NI);
    qc_kernel<<<1, 64>>>(rt_W2, rt_b2, pref, qc);
    {
        long long th = (long long)E * 16;
        omega_kernel<<<(int)((th + 255) / 256), 256>>>(Ah, At, P, Arel, Prel, eh, et, edge_type,
                                                       fp_b1, fp_W2, fp_b2, rt_b1, qc, posE,
                                                       omegaG, NR, E);
    }
    alphaeta_kernel<<<(NE + 255) / 256, 256>>>(omegaG, rowE, tpackE, epackA, epackB, NE);

    const float* srcs[3] = {entity_emb, embA, embB};
    float* dsts[3] = {embA, embB, embA};
    const int2* packs[3] = {epackA, epackA, epackB};
    for (int hop = 0; hop < 3; hop++) {
        long long th = (long long)(NE + NU) * 16;
        hop_kernel<<<(int)((th + 255) / 256), 256>>>(
            srcs[hop], relation_emb, packs[hop], rowE, itemG, wG, rowU, permE, permU,
            dsts[hop], out, out + (size_t)NE * D, entity_emb, user_emb,
            (hop == 0) ? 1 : 0, (hop == 2) ? 0 : 1, NE, NU, NR);
    }
}

// round 14
// speedup vs baseline: 1.0662x; 1.0662x over previous
#include <cuda_runtime.h>
#include <math.h>

#define D 64
#define KD 32
#define MAXU 50000
#define MAXI 30000
#define MAXENT 100000
#define MAXE 500000
#define MAXEI 1000000
#define MAXREL 10
#define GAMMA 0.2f
#define SCHUNK 1024

typedef unsigned long long u64;

// ---------------- scratch (device globals; no allocation) ----------------
__device__ float g_userWq[MAXU * D];
__device__ float g_itemWk[MAXI * D];
__device__ float g_itemWv[MAXI * D];
__device__ float g_scoresG[MAXEI];
__device__ float g_itemCoeff[MAXI];
__device__ float g_pref[D];
__device__ float g_qc[D + 1];
__device__ float g_omegaG[MAXE];
__device__ int2 g_epackA[MAXE];      // {tpack, alpha bits} per CSR-E slot
__device__ int2 g_epackB[MAXE];      // {tpack, eta bits}
__device__ float g_embA[MAXENT * D];
__device__ float g_embB[MAXENT * D];
__device__ int g_degE[MAXENT];
__device__ int g_rowE[MAXENT + 1];
__device__ int g_curE[MAXENT];
__device__ int g_posE[MAXE];
__device__ int g_tpackE[MAXE];
__device__ int g_degU[MAXU];
__device__ int g_rowU[MAXU + 1];
__device__ int g_curU[MAXU];
__device__ int g_itemG[MAXEI];
__device__ float g_wG[MAXEI];
__device__ int g_bsum[1024];
__device__ int g_boff[1024];
// precomputed per-entity tables
__device__ float g_Ah[MAXENT * D];
__device__ float g_At[MAXENT * D];
__device__ float g_P[MAXENT * D];
__device__ float g_Arel[MAXREL * D];
__device__ float g_Prel[MAXREL * D];

// ---------------- helpers ----------------
__device__ __forceinline__ float n2n(float x) {
    if (x != x) return 0.f;
    if (x == INFINITY) return 1e4f;
    if (x == -INFINITY) return 1e-4f;
    return x;
}
__device__ __forceinline__ float sigm(float x) {
    return __fdividef(1.f, 1.f + __expf(-x));
}
__device__ __forceinline__ u64 pack2(float x, float y) {
    u64 r;
    asm("mov.b64 %0, {%1, %2};" : "=l"(r) : "f"(x), "f"(y));
    return r;
}
__device__ __forceinline__ u64 ffma2(u64 a, u64 b, u64 c) {
    u64 d;
    asm("fma.rn.f32x2 %0, %1, %2, %3;" : "=l"(d) : "l"(a), "l"(b), "l"(c));
    return d;
}
// reduce over 16-lane subwarp (both halves run identical uniform pattern)
__device__ __forceinline__ float red16(float v) {
#pragma unroll
    for (int o = 8; o; o >>= 1) v += __shfl_xor_sync(0xffffffffu, v, o);
    return v;
}
// full-warp reduce
__device__ __forceinline__ float red32(float v) {
#pragma unroll
    for (int o = 16; o; o >>= 1) v += __shfl_xor_sync(0xffffffffu, v, o);
    return v;
}

// ---------------- init ----------------
__global__ void zero_kernel(int* degE, int* degU, float* ic, float* pref,
                            int NE, int NU, int NI) {
    int i = blockIdx.x * blockDim.x + threadIdx.x;
    if (i < NE) degE[i] = 0;
    if (i < NU) degU[i] = 0;
    if (i < NI) ic[i] = 0.f;
    if (i < 64) pref[i] = 0.f;
}

__global__ void hist2_kernel(const int* __restrict__ eh, const int* __restrict__ users,
                             int* degE, int* degU, int E, int EI) {
    int i = blockIdx.x * blockDim.x + threadIdx.x;
    if (i < E) atomicAdd(&degE[eh[i]], 1);
    else if (i < E + EI) atomicAdd(&degU[users[i - E]], 1);
}

// ---------------- 3-phase parallel exclusive scan (E and U fused) ----------
__global__ void bsum_kernel(const int* __restrict__ degE, int NE,
                            const int* __restrict__ degU, int NU,
                            int* bsum, int nBE) {
    __shared__ int wsum[32];
    int b = blockIdx.x;
    bool isE = b < nBE;
    const int* deg = isE ? degE : degU;
    int n = isE ? NE : NU;
    int base = (isE ? b : (b - nBE)) * SCHUNK;
    int i = base + threadIdx.x;
    int v = (i < n) ? deg[i] : 0;
    int lane = threadIdx.x & 31, wid = threadIdx.x >> 5;
#pragma unroll
    for (int o = 16; o; o >>= 1) v += __shfl_xor_sync(0xffffffffu, v, o);
    if (lane == 0) wsum[wid] = v;
    __syncthreads();
    if (wid == 0) {
        int s = wsum[lane];
#pragma unroll
        for (int o = 16; o; o >>= 1) s += __shfl_xor_sync(0xffffffffu, s, o);
        if (lane == 0) bsum[b] = s;
    }
}

__global__ void bscan_kernel(const int* __restrict__ bsum, int* boff, int nBE, int nB,
                             int* rowE, int NE, int* rowU, int NU) {
    __shared__ int sh[1024];
    int tid = threadIdx.x;
    for (int i = tid; i < nB; i += blockDim.x) sh[i] = bsum[i];
    __syncthreads();
    if (tid == 0) {
        int acc = 0;
        for (int i = 0; i < nBE; i++) { int v = sh[i]; sh[i] = acc; acc += v; }
        rowE[NE] = acc;
    }
    if (tid == 1) {
        int acc = 0;
        for (int i = nBE; i < nB; i++) { int v = sh[i]; sh[i] = acc; acc += v; }
        rowU[NU] = acc;
    }
    __syncthreads();
    for (int i = tid; i < nB; i += blockDim.x) boff[i] = sh[i];
}

__global__ void bexpand_kernel(const int* __restrict__ degE, int NE,
                               const int* __restrict__ degU, int NU,
                               const int* __restrict__ boff, int nBE,
                               int* rowE, int* rowU, int* curE, int* curU) {
    __shared__ int wsum[32];
    int b = blockIdx.x;
    bool isE = b < nBE;
    const int* deg = isE ? degE : degU;
    int n = isE ? NE : NU;
    int* row = isE ? rowE : rowU;
    int* cur = isE ? curE : curU;
    int base = (isE ? b : (b - nBE)) * SCHUNK;
    int i = base + threadIdx.x;
    int v = (i < n) ? deg[i] : 0;
    int lane = threadIdx.x & 31, wid = threadIdx.x >> 5;
    int s = v;
#pragma unroll
    for (int o = 1; o < 32; o <<= 1) {
        int t = __shfl_up_sync(0xffffffffu, s, o);
        if (lane >= o) s += t;
    }
    if (lane == 31) wsum[wid] = s;
    __syncthreads();
    if (wid == 0) {
        int ws = wsum[lane];
#pragma unroll
        for (int o = 1; o < 32; o <<= 1) {
            int t = __shfl_up_sync(0xffffffffu, ws, o);
            if (lane >= o) ws += t;
        }
        wsum[lane] = ws;
    }
    __syncthreads();
    int excl = ((wid == 0) ? 0 : wsum[wid - 1]) + s - v + boff[b];
    if (i < n) {
        row[i] = excl;
        cur[i] = excl;
    }
}

__global__ void fill2_kernel(const int* __restrict__ eh, const int* __restrict__ et,
                             const int* __restrict__ etype, int* curE, int* posE, int* tpackE,
                             int E,
                             const int* __restrict__ users, const int* __restrict__ items,
                             const float* __restrict__ w, int* curU,
                             int* itemG, float* wG, int EI) {
    int i = blockIdx.x * blockDim.x + threadIdx.x;
    if (i < E) {
        int p = atomicAdd(&curE[eh[i]], 1);
        posE[i] = p;
        tpackE[p] = et[i] | ((etype[i] - 1) << 20);
    } else if (i < E + EI) {
        int e = i - E;
        int p = atomicAdd(&curU[users[e]], 1);
        itemG[p] = items[e];
        wG[p] = w[e];
    }
}

// ---------------- entity precompute: Ah, At, P ----------------
__global__ void entpre_kernel(const float* __restrict__ ent_real,
                              const float* __restrict__ ent_imag,
                              const float* __restrict__ fpW1,
                              const float* __restrict__ rtW1,
                              float* __restrict__ Ah, float* __restrict__ At,
                              float* __restrict__ P, int NE) {
    __shared__ float sWa[64 * 64];
    __shared__ float sWb[64 * 64];
    __shared__ float sWp[64 * 64];
    __shared__ float sX[32 * 64];
    int tid = threadIdx.x;  // 1024
    for (int i = tid; i < 4096; i += 1024) {
        sWa[i] = fpW1[i];
        sWb[i] = fpW1[128 * 64 + i];
        sWp[i] = rtW1[i];
    }
    int rowBase = blockIdx.x * 32;
    for (int i = tid; i < 32 * 64; i += 1024) {
        int rl = i >> 6, k = i & 63;
        int n = rowBase + rl;
        float v = 0.f;
        if (n < NE) v = (k < 32) ? ent_real[n * KD + k] : ent_imag[n * KD + (k - 32)];
        sX[i] = v;
    }
    __syncthreads();
    int rl = tid >> 5, jp = tid & 31;
    int n = rowBase + rl;
    if (n >= NE) return;
    u64 a0 = 0, a1 = 0, a2 = 0;
    const u64* wa = (const u64*)sWa;
    const u64* wb = (const u64*)sWb;
    const u64* wp = (const u64*)sWp;
#pragma unroll 8
    for (int k = 0; k < 64; k++) {
        float xv = sX[rl * 64 + k];
        u64 xx = pack2(xv, xv);
        a0 = ffma2(xx, wa[k * 32 + jp], a0);
        a1 = ffma2(xx, wb[k * 32 + jp], a1);
        a2 = ffma2(xx, wp[k * 32 + jp], a2);
    }
    ((u64*)Ah)[n * 32 + jp] = a0;
    ((u64*)At)[n * 32 + jp] = a1;
    ((u64*)P)[n * 32 + jp] = a2;
}

// ---------------- relation precompute ----------------
__global__ void relpre_kernel(const float* __restrict__ rel_real,
                              const float* __restrict__ rel_imag,
                              const float* __restrict__ fpW1,
                              const float* __restrict__ rtW1,
                              float* __restrict__ Arel, float* __restrict__ Prel, int NR) {
    int tid = threadIdx.x;
    int r = tid >> 6, j = tid & 63;
    if (r >= NR) return;
    float a = 0.f, p = 0.f;
    for (int k = 0; k < 64; k++) {
        float xv = (k < 32) ? rel_real[r * KD + k] : rel_imag[r * KD + (k - 32)];
        a += xv * fpW1[(64 + k) * 64 + j];
        p += xv * rtW1[k * 64 + j];
    }
    Arel[r * 64 + j] = a;
    Prel[r * 64 + j] = p;
}

// ---------------- merged projections: blocks [0,gU) do Q, [gU,gU+gI) do K+V
__global__ void gemmQKV_kernel(const float* __restrict__ Xu, const float* __restrict__ Wq,
                               const float* __restrict__ Xi, const float* __restrict__ Wk,
                               const float* __restrict__ Wv,
                               float* __restrict__ Yq, float* __restrict__ Yk,
                               float* __restrict__ Yv, int NU, int NI, int gU) {
    __shared__ float sW0[64 * 64];
    __shared__ float sW1[64 * 64];
    __shared__ float sX[16 * 64];
    int tid = threadIdx.x;
    int b = blockIdx.x;
    int r = tid >> 6, j = tid & 63;
    if (b < gU) {
        for (int i = tid; i < 4096; i += 1024) sW0[i] = Wq[i];
        int row = b * 16 + r;
        if (row < NU) sX[r * 64 + j] = Xu[row * 64 + j];
        __syncthreads();
        if (row < NU) {
            float acc = 0.f;
#pragma unroll
            for (int k = 0; k < 64; k++) acc += sX[r * 64 + k] * sW0[k * 64 + j];
            Yq[row * 64 + j] = acc;
        }
    } else {
        for (int i = tid; i < 4096; i += 1024) {
            sW0[i] = Wk[i];
            sW1[i] = Wv[i];
        }
        int row = (b - gU) * 16 + r;
        if (row < NI) sX[r * 64 + j] = Xi[row * 64 + j];
        __syncthreads();
        if (row < NI) {
            float ak = 0.f, av = 0.f;
#pragma unroll
            for (int k = 0; k < 64; k++) {
                float xv = sX[r * 64 + k];
                ak += xv * sW0[k * 64 + j];
                av += xv * sW1[k * 64 + j];
            }
            Yk[row * 64 + j] = ak;
            Yv[row * 64 + j] = av;
        }
    }
}

// ---------------- fused miner v2: warp per user, q register-resident ------
// pass1: batched (unroll-4, independent chains) dots -> scoresG
// pass2/3: softmax + coeff scatter reading scoresG from L1
__global__ void miner2_kernel(const float* __restrict__ uq, const float* __restrict__ ik,
                              const int* __restrict__ rowU, const int* __restrict__ itemG,
                              const float* __restrict__ wG,
                              float* __restrict__ scoresG, float* itemCoeff, int NU) {
    int gw = (blockIdx.x * blockDim.x + threadIdx.x) >> 5;
    int lane = threadIdx.x & 31;
    if (gw >= NU) return;
    int u = gw;
    int s = rowU[u], e = rowU[u + 1];
    int deg = e - s;
    if (deg == 0) return;
    float2 q = ((const float2*)uq)[(size_t)u * 32 + lane];
    const float2* ik2 = (const float2*)ik;

    // pass 1: scores (4 independent edge chains per iteration)
    int i = s;
    for (; i + 4 <= e; i += 4) {
        int it0 = itemG[i], it1 = itemG[i + 1], it2 = itemG[i + 2], it3 = itemG[i + 3];
        float2 k0 = ik2[(size_t)it0 * 32 + lane];
        float2 k1 = ik2[(size_t)it1 * 32 + lane];
        float2 k2 = ik2[(size_t)it2 * 32 + lane];
        float2 k3 = ik2[(size_t)it3 * 32 + lane];
        float d0 = q.x * k0.x + q.y * k0.y;
        float d1 = q.x * k1.x + q.y * k1.y;
        float d2 = q.x * k2.x + q.y * k2.y;
        float d3 = q.x * k3.x + q.y * k3.y;
        d0 = red32(d0);
        d1 = red32(d1);
        d2 = red32(d2);
        d3 = red32(d3);
        if (lane < 4) {
            float dj = (lane == 0) ? d0 : (lane == 1) ? d1 : (lane == 2) ? d2 : d3;
            scoresG[i + lane] = dj * 0.125f * wG[i + lane];
        }
    }
    for (; i < e; i++) {
        float2 k0 = ik2[(size_t)itemG[i] * 32 + lane];
        float d0 = red32(q.x * k0.x + q.y * k0.y);
        if (lane == 0) scoresG[i] = d0 * 0.125f * wG[i];
    }
    __threadfence_block();
    __syncwarp();

    // pass 2: softmax normalizers
    float m = -INFINITY;
    for (int j = s + lane; j < e; j += 32) m = fmaxf(m, scoresG[j]);
#pragma unroll
    for (int o = 16; o; o >>= 1) m = fmaxf(m, __shfl_xor_sync(0xffffffffu, m, o));
    float den = 0.f;
    for (int j = s + lane; j < e; j += 32) den += __expf(scoresG[j] - m);
    den = red32(den);
    float invc = __fdividef(1.f, den * fmaxf((float)deg, 1.f));
    // pass 3: coeff scatter
    for (int j = s + lane; j < e; j += 32)
        atomicAdd(&itemCoeff[itemG[j]], __expf(scoresG[j] - m) * invc);
}

__global__ void pref_kernel(const float* __restrict__ itemCoeff,
                            const float* __restrict__ itemWv, float* pref, int NI) {
    int j = threadIdx.x;  // 64
    float acc = 0.f;
    for (int i = blockIdx.x; i < NI; i += gridDim.x)
        acc += itemCoeff[i] * itemWv[i * 64 + j];
    atomicAdd(&pref[j], acc);
}

__global__ void qc_kernel(const float* __restrict__ rtW2, const float* __restrict__ rtb2,
                          const float* __restrict__ pref, float* qc) {
    __shared__ float sp[64];
    __shared__ float red[64];
    int j = threadIdx.x;
    sp[j] = pref[j];
    __syncthreads();
    float q = 0.f;
#pragma unroll
    for (int k = 0; k < 64; k++) q += rtW2[j * 64 + k] * sp[k];
    qc[j] = q * 0.125f;
    red[j] = rtb2[j] * sp[j];
    __syncthreads();
    if (j == 0) {
        float c = 0.f;
        for (int k = 0; k < 64; k++) c += red[k];
        qc[64] = c * 0.125f;
    }
}

// ---------------- omega: 16-lane subwarp per edge ----------------
__global__ void omega_kernel(const float* __restrict__ Ah, const float* __restrict__ At,
                             const float* __restrict__ P,
                             const float* __restrict__ Arel, const float* __restrict__ Prel,
                             const int* __restrict__ eh, const int* __restrict__ et,
                             const int* __restrict__ etype,
                             const float* __restrict__ fpb1, const float* __restrict__ fpW2,
                             const float* __restrict__ fpb2, const float* __restrict__ rtb1,
                             const float* __restrict__ qc, const int* __restrict__ posE,
                             float* __restrict__ omegaG, int NR, int E) {
    __shared__ float sAr[MAXREL * 64];
    __shared__ float sPr[MAXREL * 64];
    __shared__ float sb1[64], srb1[64], sq[64];
    __shared__ float sW2c0[64], sW2c1[64], sW2c2[64];
    __shared__ float sb2[3];
    __shared__ float sc0;
    int tid = threadIdx.x;
    for (int i = tid; i < NR * 64; i += blockDim.x) {
        sAr[i] = Arel[i];
        sPr[i] = Prel[i];
    }
    for (int i = tid; i < 64; i += blockDim.x) {
        sb1[i] = fpb1[i];
        srb1[i] = rtb1[i];
        sq[i] = qc[i];
        sW2c0[i] = fpW2[i * 3 + 0];
        sW2c1[i] = fpW2[i * 3 + 1];
        sW2c2[i] = fpW2[i * 3 + 2];
    }
    if (tid < 3) sb2[tid] = fpb2[tid];
    if (tid == 0) sc0 = qc[64];
    __syncthreads();

    int g = blockIdx.x * blockDim.x + tid;
    int e = g >> 4, lane = g & 15;
    if (e >= E) return;
    int h = eh[e], t = et[e], r = etype[e] - 1;

    float4 a = ((const float4*)(Ah + (size_t)h * 64))[lane];
    float4 c = ((const float4*)(At + (size_t)t * 64))[lane];
    float4 ph = ((const float4*)(P + (size_t)h * 64))[lane];
    float4 pt = ((const float4*)(P + (size_t)t * 64))[lane];
    float4 b = ((const float4*)(sAr + r * 64))[lane];
    float4 bb = ((const float4*)sb1)[lane];
    float s0 = sigm(a.x + b.x + c.x + bb.x);
    float s1 = sigm(a.y + b.y + c.y + bb.y);
    float s2 = sigm(a.z + b.z + c.z + bb.z);
    float s3 = sigm(a.w + b.w + c.w + bb.w);

    float4 w20 = ((const float4*)sW2c0)[lane];
    float4 w21 = ((const float4*)sW2c1)[lane];
    float4 w22 = ((const float4*)sW2c2)[lane];
    float z0 = s0 * w20.x + s1 * w20.y + s2 * w20.z + s3 * w20.w;
    float z1 = s0 * w21.x + s1 * w21.y + s2 * w21.z + s3 * w21.w;
    float z2 = s0 * w22.x + s1 * w22.y + s2 * w22.z + s3 * w22.w;
    z0 = red16(z0);
    z1 = red16(z1);
    z2 = red16(z2);
    z0 += sb2[0];
    z1 += sb2[1];
    z2 += sb2[2];
    float mx = fmaxf(z0, fmaxf(z1, z2));
    float e0 = __expf(z0 - mx), e1 = __expf(z1 - mx), e2 = __expf(z2 - mx);
    float inv = __fdividef(1.f, e0 + e1 + e2);
    float w0 = e0 * inv, w1 = e1 * inv, w2 = e2 * inv;

    float4 pr = ((const float4*)(sPr + r * 64))[lane];
    float4 rb = ((const float4*)srb1)[lane];
    float4 qv = ((const float4*)sq)[lane];
    float om = qv.x * sigm(w0 * ph.x + w1 * pr.x + w2 * pt.x + rb.x)
             + qv.y * sigm(w0 * ph.y + w1 * pr.y + w2 * pt.y + rb.y)
             + qv.z * sigm(w0 * ph.z + w1 * pr.z + w2 * pt.z + rb.z)
             + qv.w * sigm(w0 * ph.w + w1 * pr.w + w2 * pt.w + rb.w);
    om = red16(om);
    if (lane == 0) omegaG[posE[e]] = om + sc0;
}

// ---------------- alpha / eta packed with tpack ----------------
__global__ void alphaeta_kernel(const float* __restrict__ omegaG, const int* __restrict__ rowE,
                                const int* __restrict__ tpackE,
                                int2* __restrict__ epackA, int2* __restrict__ epackB, int NE) {
    int h = blockIdx.x * blockDim.x + threadIdx.x;
    if (h >= NE) return;
    int s = rowE[h], e = rowE[h + 1];
    if (s == e) return;
    float so = 0.f;
    for (int i = s; i < e; i++) so += omegaG[i];
    float d1 = so + 1e-8f;
    float se = 0.f;
    for (int i = s; i < e; i++) {
        float a = omegaG[i] / d1;
        se += (a > GAMMA) ? a : 0.f;
    }
    float d2 = se + 1e-8f;
    for (int i = s; i < e; i++) {
        float a = omegaG[i] / d1;
        int tp = tpackE[i];
        epackA[i] = make_int2(tp, __float_as_int(a));
        float e0 = (a > GAMMA) ? a / d2 : 0.f;
        epackB[i] = make_int2(tp, __float_as_int(e0));
    }
}

// ---------------- merged hop kernel: 16-lane subwarp per row -------------
// hop0: out = base + normalized ; else: out += normalized
// writeDst==0 on the last hop (dst never read again)
__global__ void hop_kernel(const float* __restrict__ src, const float* __restrict__ relemb,
                           const int2* __restrict__ epack,
                           const int* __restrict__ rowE,
                           const int* __restrict__ itemG, const float* __restrict__ wG,
                           const int* __restrict__ rowU,
                           float* __restrict__ dst, float* __restrict__ outE,
                           float* __restrict__ outU,
                           const float* __restrict__ baseE, const float* __restrict__ baseU,
                           int hop0, int writeDst, int NE, int NU, int NR) {
    __shared__ float sRel[MAXREL * 64];
    int tid = threadIdx.x;
    for (int i = tid; i < NR * 64; i += blockDim.x) sRel[i] = relemb[i];
    __syncthreads();

    int g = blockIdx.x * blockDim.x + tid;
    int row = g >> 4, lane = g & 15;
    if (row >= NE + NU) return;
    const float4* src4 = (const float4*)src;

    if (row < NE) {
        int h = row;
        int s = rowE[h], e1 = rowE[h + 1];
        float4 acc = make_float4(0.f, 0.f, 0.f, 0.f);
        int i = s;
        for (; i + 2 <= e1; i += 2) {
            int2 p0 = epack[i], p1 = epack[i + 1];
            float r0 = __int_as_float(p0.y), r1 = __int_as_float(p1.y);
            float4 x0 = src4[(size_t)(p0.x & 0xFFFFF) * 16 + lane];
            float4 x1 = src4[(size_t)(p1.x & 0xFFFFF) * 16 + lane];
            const float4* sRel4 = (const float4*)sRel;
            float4 w0 = sRel4[(p0.x >> 20) * 16 + lane];
            float4 w1 = sRel4[(p1.x >> 20) * 16 + lane];
            acc.x += r0 * x0.x * w0.x + r1 * x1.x * w1.x;
            acc.y += r0 * x0.y * w0.y + r1 * x1.y * w1.y;
            acc.z += r0 * x0.z * w0.z + r1 * x1.z * w1.z;
            acc.w += r0 * x0.w * w0.w + r1 * x1.w * w1.w;
        }
        if (i < e1) {
            int2 p = epack[i];
            float rv = __int_as_float(p.y);
            float4 x = src4[(size_t)(p.x & 0xFFFFF) * 16 + lane];
            const float4* sRel4 = (const float4*)sRel;
            float4 w = sRel4[(p.x >> 20) * 16 + lane];
            acc.x += rv * x.x * w.x;
            acc.y += rv * x.y * w.y;
            acc.z += rv * x.z * w.z;
            acc.w += rv * x.w * w.w;
        }
        float c = fmaxf((float)(e1 - s), 1.f);
        float invc = __fdividef(1.f, c);
        acc.x *= invc; acc.y *= invc; acc.z *= invc; acc.w *= invc;
        float ss = acc.x * acc.x + acc.y * acc.y + acc.z * acc.z + acc.w * acc.w;
        ss = red16(ss);
        float inv = 1.f / fmaxf(sqrtf(ss), 1e-8f);
        float4 o;
        o.x = n2n(acc.x * inv); o.y = n2n(acc.y * inv);
        o.z = n2n(acc.z * inv); o.w = n2n(acc.w * inv);
        if (writeDst) ((float4*)dst)[(size_t)h * 16 + lane] = o;
        float4 o2 = hop0 ? ((const float4*)baseE)[(size_t)h * 16 + lane]
                         : ((float4*)outE)[(size_t)h * 16 + lane];
        o2.x += o.x; o2.y += o.y; o2.z += o.z; o2.w += o.w;
        ((float4*)outE)[(size_t)h * 16 + lane] = o2;
    } else {
        int u = row - NE;
        int s = rowU[u], e1 = rowU[u + 1];
        float4 acc = make_float4(0.f, 0.f, 0.f, 0.f);
        int i = s;
        for (; i + 4 <= e1; i += 4) {
            int it0 = itemG[i], it1 = itemG[i + 1], it2 = itemG[i + 2], it3 = itemG[i + 3];
            float w0 = wG[i], w1 = wG[i + 1], w2 = wG[i + 2], w3 = wG[i + 3];
            float4 x0 = src4[(size_t)it0 * 16 + lane];
            float4 x1 = src4[(size_t)it1 * 16 + lane];
            float4 x2 = src4[(size_t)it2 * 16 + lane];
            float4 x3 = src4[(size_t)it3 * 16 + lane];
            acc.x += w0 * x0.x + w1 * x1.x + w2 * x2.x + w3 * x3.x;
            acc.y += w0 * x0.y + w1 * x1.y + w2 * x2.y + w3 * x3.y;
            acc.z += w0 * x0.z + w1 * x1.z + w2 * x2.z + w3 * x3.z;
            acc.w += w0 * x0.w + w1 * x1.w + w2 * x2.w + w3 * x3.w;
        }
        for (; i < e1; i++) {
            int it = itemG[i];
            float wv = wG[i];
            float4 x = src4[(size_t)it * 16 + lane];
            acc.x += wv * x.x;
            acc.y += wv * x.y;
            acc.z += wv * x.z;
            acc.w += wv * x.w;
        }
        float ss = acc.x * acc.x + acc.y * acc.y + acc.z * acc.z + acc.w * acc.w;
        ss = red16(ss);
        float inv = 1.f / fmaxf(sqrtf(ss), 1e-8f);
        float4 o;
        o.x = n2n(acc.x * inv); o.y = n2n(acc.y * inv);
        o.z = n2n(acc.z * inv); o.w = n2n(acc.w * inv);
        float4 o2 = hop0 ? ((const float4*)baseU)[(size_t)u * 16 + lane]
                         : ((float4*)outU)[(size_t)u * 16 + lane];
        o2.x += o.x; o2.y += o.y; o2.z += o.z; o2.w += o.w;
        ((float4*)outU)[(size_t)u * 16 + lane] = o2;
    }
}

// ---------------- launch ----------------
extern "C" void kernel_launch(void* const* d_in, const int* in_sizes, int n_in,
                              void* d_out, int out_size) {
    const float* user_embed = (const float*)d_in[0];
    const float* item_embed = (const float*)d_in[1];
    const float* Wq = (const float*)d_in[2];
    const float* Wk = (const float*)d_in[3];
    const float* Wv = (const float*)d_in[4];
    const float* ent_real = (const float*)d_in[5];
    const float* ent_imag = (const float*)d_in[6];
    const float* rel_real = (const float*)d_in[7];
    const float* rel_imag = (const float*)d_in[8];
    const float* fp_W1 = (const float*)d_in[9];
    const float* fp_b1 = (const float*)d_in[10];
    const float* fp_W2 = (const float*)d_in[11];
    const float* fp_b2 = (const float*)d_in[12];
    const float* rt_W1 = (const float*)d_in[13];
    const float* rt_b1 = (const float*)d_in[14];
    const float* rt_W2 = (const float*)d_in[15];
    const float* rt_b2 = (const float*)d_in[16];
    const float* relation_emb = (const float*)d_in[17];
    const float* user_emb = (const float*)d_in[18];
    const float* entity_emb = (const float*)d_in[19];
    const float* inter_edge_w = (const float*)d_in[20];
    const int* edge_index = (const int*)d_in[21];
    const int* edge_type = (const int*)d_in[22];
    const int* inter_edge = (const int*)d_in[23];
    float* out = (float*)d_out;

    int NU = in_sizes[0] / D;
    int NI = in_sizes[1] / D;
    int NE = in_sizes[5] / KD;
    int NR = in_sizes[7] / KD;
    int E = in_sizes[22];
    int EI = in_sizes[20];
    const int* eh = edge_index;
    const int* et = edge_index + E;
    const int* users = inter_edge;
    const int* items = inter_edge + EI;

    float *userWq, *itemWk, *itemWv, *scoresG, *itemCoeff, *pref, *qc;
    float *omegaG, *embA, *embB, *wG;
    int2 *epackA, *epackB;
    float *Ah, *At, *P, *Arel, *Prel;
    int *degE, *rowE, *curE, *posE, *tpackE, *degU, *rowU, *curU, *itemG;
    int *bsum, *boff;
    cudaGetSymbolAddress((void**)&userWq, g_userWq);
    cudaGetSymbolAddress((void**)&itemWk, g_itemWk);
    cudaGetSymbolAddress((void**)&itemWv, g_itemWv);
    cudaGetSymbolAddress((void**)&scoresG, g_scoresG);
    cudaGetSymbolAddress((void**)&itemCoeff, g_itemCoeff);
    cudaGetSymbolAddress((void**)&pref, g_pref);
    cudaGetSymbolAddress((void**)&qc, g_qc);
    cudaGetSymbolAddress((void**)&omegaG, g_omegaG);
    cudaGetSymbolAddress((void**)&epackA, g_epackA);
    cudaGetSymbolAddress((void**)&epackB, g_epackB);
    cudaGetSymbolAddress((void**)&embA, g_embA);
    cudaGetSymbolAddress((void**)&embB, g_embB);
    cudaGetSymbolAddress((void**)&degE, g_degE);
    cudaGetSymbolAddress((void**)&rowE, g_rowE);
    cudaGetSymbolAddress((void**)&curE, g_curE);
    cudaGetSymbolAddress((void**)&posE, g_posE);
    cudaGetSymbolAddress((void**)&tpackE, g_tpackE);
    cudaGetSymbolAddress((void**)&degU, g_degU);
    cudaGetSymbolAddress((void**)&rowU, g_rowU);
    cudaGetSymbolAddress((void**)&curU, g_curU);
    cudaGetSymbolAddress((void**)&itemG, g_itemG);
    cudaGetSymbolAddress((void**)&wG, g_wG);
    cudaGetSymbolAddress((void**)&bsum, g_bsum);
    cudaGetSymbolAddress((void**)&boff, g_boff);
    cudaGetSymbolAddress((void**)&Ah, g_Ah);
    cudaGetSymbolAddress((void**)&At, g_At);
    cudaGetSymbolAddress((void**)&P, g_P);
    cudaGetSymbolAddress((void**)&Arel, g_Arel);
    cudaGetSymbolAddress((void**)&Prel, g_Prel);

    int nBE = (NE + SCHUNK - 1) / SCHUNK;
    int nBU = (NU + SCHUNK - 1) / SCHUNK;
    int nB = nBE + nBU;

    zero_kernel<<<(NE + 255) / 256, 256>>>(degE, degU, itemCoeff, pref, NE, NU, NI);
    hist2_kernel<<<(E + EI + 255) / 256, 256>>>(eh, users, degE, degU, E, EI);
    bsum_kernel<<<nB, SCHUNK>>>(degE, NE, degU, NU, bsum, nBE);
    bscan_kernel<<<1, 256>>>(bsum, boff, nBE, nB, rowE, NE, rowU, NU);
    bexpand_kernel<<<nB, SCHUNK>>>(degE, NE, degU, NU, boff, nBE, rowE, rowU, curE, curU);
    entpre_kernel<<<(NE + 31) / 32, 1024>>>(ent_real, ent_imag, fp_W1, rt_W1, Ah, At, P, NE);
    fill2_kernel<<<(E + EI + 255) / 256, 256>>>(eh, et, edge_type, curE, posE, tpackE, E,
                                                users, items, inter_edge_w, curU,
                                                itemG, wG, EI);
    relpre_kernel<<<1, NR * 64>>>(rel_real, rel_imag, fp_W1, rt_W1, Arel, Prel, NR);
    {
        int gU = (NU + 15) / 16, gI = (NI + 15) / 16;
        gemmQKV_kernel<<<gU + gI, 1024>>>(user_embed, Wq, item_embed, Wk, Wv,
                                          userWq, itemWk, itemWv, NU, NI, gU);
    }
    {
        long long th = (long long)NU * 32;
        miner2_kernel<<<(int)((th + 255) / 256), 256>>>(userWq, itemWk, rowU, itemG, wG,
                                                        scoresG, itemCoeff, NU);
    }
    pref_kernel<<<256, 64>>>(itemCoeff, itemWv, pref, NI);
    qc_kernel<<<1, 64>>>(rt_W2, rt_b2, pref, qc);
    {
        long long th = (long long)E * 16;
        omega_kernel<<<(int)((th + 255) / 256), 256>>>(Ah, At, P, Arel, Prel, eh, et, edge_type,
                                                       fp_b1, fp_W2, fp_b2, rt_b1, qc, posE,
                                                       omegaG, NR, E);
    }
    alphaeta_kernel<<<(NE + 255) / 256, 256>>>(omegaG, rowE, tpackE, epackA, epackB, NE);

    const float* srcs[3] = {entity_emb, embA, embB};
    float* dsts[3] = {embA, embB, embA};
    const int2* packs[3] = {epackA, epackA, epackB};
    for (int hop = 0; hop < 3; hop++) {
        long long th = (long long)(NE + NU) * 16;
        hop_kernel<<<(int)((th + 255) / 256), 256>>>(
            srcs[hop], relation_emb, packs[hop], rowE, itemG, wG, rowU,
            dsts[hop], out, out + (size_t)NE * D, entity_emb, user_emb,
            (hop == 0) ? 1 : 0, (hop == 2) ? 0 : 1, NE, NU, NR);
    }
}